// round 1
// baseline (speedup 1.0000x reference)
#include <cuda_runtime.h>

// RegLSTM: B=2098 sequences, T=2048 steps, HID=8, INP=3, OUT=1.
// Mapping: 8 lanes per batch element (lane k = hidden unit k, owns gates i,f,g,o for k).
// 4 elements per warp, 16 per 128-thread block, grid=132 blocks (1/SM).
// Cross-lane traffic: one 8-way h-allgather per step (serves recurrence of step t AND
// head of step t-1), 3 bfly shuffles for the head dot-product. Output staged in a
// per-lane register ring, flushed as a coalesced 8-float store every 8 steps.

#define B_   2098
#define T_   2048
#define L2E_ 1.4426950408889634f

__device__ __forceinline__ float ex2a(float x) {
    float r; asm("ex2.approx.f32 %0, %1;" : "=f"(r) : "f"(x)); return r;
}
__device__ __forceinline__ float rcpa(float x) {
    float r; asm("rcp.approx.f32 %0, %1;" : "=f"(r) : "f"(x)); return r;
}
// sigmoid(x) = 1/(1+2^(-x*log2e))  -- 2 MUFU + 2 FMA-pipe ops, ~1e-7 rel err
__device__ __forceinline__ float sigm(float x) {
    return rcpa(1.0f + ex2a(-L2E_ * x));
}
// tanh(x) = 2*sigmoid(2x)-1. Saturates correctly at +/-1 for large |x|.
__device__ __forceinline__ float tanha(float x) {
    float s = rcpa(1.0f + ex2a(-2.0f * L2E_ * x));
    return fmaf(2.0f, s, -1.0f);
}

__global__ __launch_bounds__(128) void reglstm_kernel(
    const float* __restrict__ x,      // [B, T, 3]
    const float* __restrict__ W_ih,   // [32, 3]
    const float* __restrict__ W_hh,   // [32, 8]
    const float* __restrict__ b_ih,   // [32]
    const float* __restrict__ b_hh,   // [32]
    const float* __restrict__ W1,     // [8, 8]
    const float* __restrict__ b1,     // [8]
    const float* __restrict__ W2,     // [1, 8]
    const float* __restrict__ b2,     // [1]
    float* __restrict__ out)          // [B, T]
{
    const int tid = threadIdx.x;
    const int g   = blockIdx.x * (blockDim.x >> 3) + (tid >> 3);  // batch element
    const int k   = tid & 7;                                       // hidden unit
    if (g >= B_) return;
    const unsigned mask = 0xFFu << (tid & 24);  // 8-lane group mask within warp

    // ---- lane-constant weights (gate order: i, f, g, o; row = G*8 + k) ----
    float wi[4][3], bias[4], whh[4][8];
    #pragma unroll
    for (int G = 0; G < 4; G++) {
        const int row = G * 8 + k;
        wi[G][0] = W_ih[row * 3 + 0];
        wi[G][1] = W_ih[row * 3 + 1];
        wi[G][2] = W_ih[row * 3 + 2];
        bias[G]  = b_ih[row] + b_hh[row];
        #pragma unroll
        for (int j = 0; j < 8; j++) whh[G][j] = W_hh[row * 8 + j];
    }
    float w1[8];
    #pragma unroll
    for (int j = 0; j < 8; j++) w1[j] = W1[k * 8 + j];
    const float b1k = b1[k];
    const float w2k = W2[k];
    const float b2v = b2[0];

    const float* __restrict__ xr = x + (size_t)g * T_ * 3;
    float* __restrict__ orow = out + (size_t)g * T_;

    float h = 0.0f, c = 0.0f, y_keep = 0.0f;
    // software-pipelined x (prefetch next step during compute)
    float x0 = xr[0], x1 = xr[1], x2 = xr[2];

    for (int t = 0; t < T_; t++) {
        // allgather h_{t-1} across the 8-lane group (also feeds head of step t-1)
        float hj[8];
        #pragma unroll
        for (int j = 0; j < 8; j++) hj[j] = __shfl_sync(mask, h, j, 8);

        // prefetch x for t+1 (clamped at the end; value unused there)
        const int tn = (t + 1 < T_) ? (t + 1) : t;
        const float nx0 = xr[tn * 3 + 0];
        const float nx1 = xr[tn * 3 + 1];
        const float nx2 = xr[tn * 3 + 2];

        // gate pre-activations: x-projection + bias
        float gi = fmaf(wi[0][0], x0, fmaf(wi[0][1], x1, fmaf(wi[0][2], x2, bias[0])));
        float gf = fmaf(wi[1][0], x0, fmaf(wi[1][1], x1, fmaf(wi[1][2], x2, bias[1])));
        float gg = fmaf(wi[2][0], x0, fmaf(wi[2][1], x1, fmaf(wi[2][2], x2, bias[2])));
        float go = fmaf(wi[3][0], x0, fmaf(wi[3][1], x1, fmaf(wi[3][2], x2, bias[3])));
        // recurrent projection (4 independent chains -> ILP for the FMA pipe)
        #pragma unroll
        for (int j = 0; j < 8; j++) {
            gi = fmaf(whh[0][j], hj[j], gi);
            gf = fmaf(whh[1][j], hj[j], gf);
            gg = fmaf(whh[2][j], hj[j], gg);
            go = fmaf(whh[3][j], hj[j], go);
        }

        const float iv = sigm(gi);
        const float fv = sigm(gf);
        const float gv = tanha(gg);
        const float ov = sigm(go);
        c = fmaf(fv, c, iv * gv);
        h = ov * tanha(c);

        // regression head for step t-1 (reuses hj gathered above)
        if (t > 0) {
            float z = b1k;
            #pragma unroll
            for (int j = 0; j < 8; j++) z = fmaf(w1[j], hj[j], z);
            z = tanha(z);
            float p = w2k * z;
            p += __shfl_xor_sync(mask, p, 1, 8);
            p += __shfl_xor_sync(mask, p, 2, 8);
            p += __shfl_xor_sync(mask, p, 4, 8);
            const float yv = p + b2v;
            const int slot = (t - 1) & 7;
            if (k == slot) y_keep = yv;
            if (slot == 7) orow[(t - 8) + k] = y_keep;  // coalesced 8-float flush
        }

        x0 = nx0; x1 = nx1; x2 = nx2;
    }

    // epilogue: head for step T-1, then flush the final 8 outputs
    {
        float hj[8];
        #pragma unroll
        for (int j = 0; j < 8; j++) hj[j] = __shfl_sync(mask, h, j, 8);
        float z = b1k;
        #pragma unroll
        for (int j = 0; j < 8; j++) z = fmaf(w1[j], hj[j], z);
        z = tanha(z);
        float p = w2k * z;
        p += __shfl_xor_sync(mask, p, 1, 8);
        p += __shfl_xor_sync(mask, p, 2, 8);
        p += __shfl_xor_sync(mask, p, 4, 8);
        const float yv = p + b2v;
        if (k == 7) y_keep = yv;             // slot of step T-1 is 7
        orow[(T_ - 8) + k] = y_keep;         // steps T-8 .. T-1
    }
}

extern "C" void kernel_launch(void* const* d_in, const int* in_sizes, int n_in,
                              void* d_out, int out_size) {
    const float* x    = (const float*)d_in[0];
    const float* W_ih = (const float*)d_in[1];
    const float* W_hh = (const float*)d_in[2];
    const float* b_ih = (const float*)d_in[3];
    const float* b_hh = (const float*)d_in[4];
    const float* W1   = (const float*)d_in[5];
    const float* b1   = (const float*)d_in[6];
    const float* W2   = (const float*)d_in[7];
    const float* b2   = (const float*)d_in[8];
    float* out = (float*)d_out;

    const int elems_per_block = 128 / 8;  // 16
    const int grid = (B_ + elems_per_block - 1) / elems_per_block;  // 132
    reglstm_kernel<<<grid, 128>>>(x, W_ih, W_hh, b_ih, b_hh, W1, b1, W2, b2, out);
}

// round 2
// speedup vs baseline: 1.6221x; 1.6221x over previous
#include <cuda_runtime.h>

// RegLSTM: B=2098, T=2048, HID=8, INP=3, OUT=1.
// 8 lanes per element (lane k = hidden unit k, owns gates i,f,g,o of unit k).
// 4 elements/warp, 16/block, 132 blocks (1/SM). ~1 warp/SMSP -> latency-bound,
// so this version minimizes the exposed per-step serial chain:
//  - time loop unrolled x8, branch-free body (compile-time output slots)
//  - x loaded as 6x float4 / 8 steps, x-projection hoisted (independent work)
//  - weights pre-scaled by -log2e (sigmoid gates) / -2log2e (tanh paths) so each
//    activation is bare ex2 -> add -> rcp
//  - cell kept in log-domain c' = -2*log2e*c so tanh(c) needs no leading FMA
//  - each 8-FMA recurrent chain split into two 4-chains + add (depth 32 -> 20)

#define B_   2098
#define T_   2048
#define L2E_ 1.4426950408889634f

__device__ __forceinline__ float ex2a(float x) {
    float r; asm("ex2.approx.f32 %0, %1;" : "=f"(r) : "f"(x)); return r;
}
__device__ __forceinline__ float rcpa(float x) {
    float r; asm("rcp.approx.f32 %0, %1;" : "=f"(r) : "f"(x)); return r;
}

__global__ __launch_bounds__(128) void reglstm_kernel(
    const float* __restrict__ x,      // [B, T, 3]
    const float* __restrict__ W_ih,   // [32, 3]
    const float* __restrict__ W_hh,   // [32, 8]
    const float* __restrict__ b_ih,   // [32]
    const float* __restrict__ b_hh,   // [32]
    const float* __restrict__ W1,     // [8, 8]
    const float* __restrict__ b1,     // [8]
    const float* __restrict__ W2,     // [1, 8]
    const float* __restrict__ b2,     // [1]
    float* __restrict__ out)          // [B, T]
{
    const int tid = threadIdx.x;
    const int g   = blockIdx.x * (blockDim.x >> 3) + (tid >> 3);
    const int k   = tid & 7;
    if (g >= B_) return;
    const unsigned mask = 0xFFu << (tid & 24);

    // ---- pre-scaled lane-constant weights ----
    // G: 0=i, 1=f, 2=g(tanh), 3=o. Scale -L2E for sigmoid gates, -2L2E for g.
    float wi[4][3], bs[4], whh[4][8];
    #pragma unroll
    for (int G = 0; G < 4; G++) {
        const float sc  = (G == 2) ? (-2.0f * L2E_) : (-L2E_);
        const int  row  = G * 8 + k;
        wi[G][0] = sc * W_ih[row * 3 + 0];
        wi[G][1] = sc * W_ih[row * 3 + 1];
        wi[G][2] = sc * W_ih[row * 3 + 2];
        bs[G]    = sc * (b_ih[row] + b_hh[row]);
        #pragma unroll
        for (int j = 0; j < 8; j++) whh[G][j] = sc * W_hh[row * 8 + j];
    }
    // head: z' = -2L2E*(W1 h + b1); tanh(z) = 2*rcp(1+ex2(z')) - 1
    // p = W2[k]*tanh = fma(2*W2[k], s, -W2[k])
    float w1s[8];
    #pragma unroll
    for (int j = 0; j < 8; j++) w1s[j] = (-2.0f * L2E_) * W1[k * 8 + j];
    const float b1s  = (-2.0f * L2E_) * b1[k];
    const float w2k2 = 2.0f * W2[k];
    const float w2kn = -W2[k];
    const float b2v  = b2[0];

    const float* __restrict__ xr = x + (size_t)g * T_ * 3;
    float* __restrict__ orow = out + (size_t)g * T_;

    float h = 0.0f, cl = 0.0f, y_keep = 0.0f;  // cl = -2L2E * c (log-domain cell)

    for (int it = 0; it < T_ / 8; it++) {
        // ---- load 8 steps of x (24 floats, 6x LDG.128), hoist x-projection ----
        const float4* __restrict__ xv = (const float4*)(xr + it * 24);
        float4 q0 = xv[0], q1 = xv[1], q2 = xv[2], q3 = xv[3], q4 = xv[4], q5 = xv[5];
        float xs[24] = { q0.x,q0.y,q0.z,q0.w, q1.x,q1.y,q1.z,q1.w,
                         q2.x,q2.y,q2.z,q2.w, q3.x,q3.y,q3.z,q3.w,
                         q4.x,q4.y,q4.z,q4.w, q5.x,q5.y,q5.z,q5.w };
        float gx[8][4];
        #pragma unroll
        for (int s = 0; s < 8; s++) {
            #pragma unroll
            for (int G = 0; G < 4; G++) {
                gx[s][G] = fmaf(wi[G][0], xs[s*3],
                           fmaf(wi[G][1], xs[s*3+1],
                           fmaf(wi[G][2], xs[s*3+2], bs[G])));
            }
        }

        #pragma unroll
        for (int s = 0; s < 8; s++) {
            // allgather h_{t-1}
            float hj[8];
            #pragma unroll
            for (int j = 0; j < 8; j++) hj[j] = __shfl_sync(mask, h, j, 8);

            // ---- regression head for step t-1 (slot (s-1)&7), off critical path ----
            const bool do_head = (s > 0) || (it > 0);
            if (do_head) {
                float za = fmaf(w1s[0], hj[0], fmaf(w1s[1], hj[1],
                           fmaf(w1s[2], hj[2], fmaf(w1s[3], hj[3], b1s))));
                float zb = fmaf(w1s[5], hj[5], fmaf(w1s[6], hj[6],
                           fmaf(w1s[7], hj[7], w1s[4] * hj[4])));
                float sz = rcpa(1.0f + ex2a(za + zb));
                float p  = fmaf(w2k2, sz, w2kn);
                p += __shfl_xor_sync(mask, p, 1, 8);
                p += __shfl_xor_sync(mask, p, 2, 8);
                p += __shfl_xor_sync(mask, p, 4, 8);
                const float yv = p + b2v;
                const int slot = (s - 1) & 7;   // compile-time
                if (k == slot) y_keep = yv;
            }
            if (s == 0 && it > 0)
                orow[(it - 1) * 8 + k] = y_keep;  // flush previous 8 outputs

            // ---- recurrent projection: two 4-chains + add per gate ----
            float pre[4];
            #pragma unroll
            for (int G = 0; G < 4; G++) {
                float a0 = fmaf(whh[G][3], hj[3], fmaf(whh[G][2], hj[2],
                           fmaf(whh[G][1], hj[1], fmaf(whh[G][0], hj[0], gx[s][G]))));
                float a1 = fmaf(whh[G][7], hj[7], fmaf(whh[G][6], hj[6],
                           fmaf(whh[G][5], hj[5], whh[G][4] * hj[4])));
                pre[G] = a0 + a1;
            }

            // ---- activations: s = rcp(1 + ex2(pre)) (pre already scaled) ----
            const float si = rcpa(1.0f + ex2a(pre[0]));   // sigmoid(i)
            const float sf = rcpa(1.0f + ex2a(pre[1]));   // sigmoid(f)
            const float sg = rcpa(1.0f + ex2a(pre[2]));   // (tanh(g)+1)/2
            const float so = rcpa(1.0f + ex2a(pre[3]));   // sigmoid(o)

            // log-domain cell: cl = f*cl + i * gvp, gvp = -2L2E*(2*sg-1)
            const float gvp = fmaf(-4.0f * L2E_, sg, 2.0f * L2E_);
            cl = fmaf(sf, cl, si * gvp);

            // tanh(c) = 2*rcp(1+ex2(cl)) - 1 ; h = o*tanh(c) = fma(2o, sc, -o)
            const float scc = rcpa(1.0f + ex2a(cl));
            const float o2  = so + so;     // off-chain
            const float on  = -so;         // off-chain
            h = fmaf(o2, scc, on);
        }
    }

    // ---- epilogue: head for step T-1 (slot 7), flush last block ----
    {
        float hj[8];
        #pragma unroll
        for (int j = 0; j < 8; j++) hj[j] = __shfl_sync(mask, h, j, 8);
        float za = fmaf(w1s[0], hj[0], fmaf(w1s[1], hj[1],
                   fmaf(w1s[2], hj[2], fmaf(w1s[3], hj[3], b1s))));
        float zb = fmaf(w1s[5], hj[5], fmaf(w1s[6], hj[6],
                   fmaf(w1s[7], hj[7], w1s[4] * hj[4])));
        float sz = rcpa(1.0f + ex2a(za + zb));
        float p  = fmaf(w2k2, sz, w2kn);
        p += __shfl_xor_sync(mask, p, 1, 8);
        p += __shfl_xor_sync(mask, p, 2, 8);
        p += __shfl_xor_sync(mask, p, 4, 8);
        const float yv = p + b2v;
        if (k == 7) y_keep = yv;
        orow[T_ - 8 + k] = y_keep;
    }
}

extern "C" void kernel_launch(void* const* d_in, const int* in_sizes, int n_in,
                              void* d_out, int out_size) {
    const float* x    = (const float*)d_in[0];
    const float* W_ih = (const float*)d_in[1];
    const float* W_hh = (const float*)d_in[2];
    const float* b_ih = (const float*)d_in[3];
    const float* b_hh = (const float*)d_in[4];
    const float* W1   = (const float*)d_in[5];
    const float* b1   = (const float*)d_in[6];
    const float* W2   = (const float*)d_in[7];
    const float* b2   = (const float*)d_in[8];
    float* out = (float*)d_out;

    const int elems_per_block = 128 / 8;  // 16
    const int grid = (B_ + elems_per_block - 1) / elems_per_block;  // 132
    reglstm_kernel<<<grid, 128>>>(x, W_ih, W_hh, b_ih, b_hh, W1, b1, W2, b2, out);
}